// round 5
// baseline (speedup 1.0000x reference)
#include <cuda_runtime.h>

// 2-layer LSTM (B=2048, T=1024, I=6, H=38) + final projection (C=8), fp32.
// Persistent blocks: each block owns 8 batch rows for the whole time loop.
// Thread = (batch-pair, padded hidden unit). Gate-pair packed f32x2 FMAs:
//   acc_if = {gate_i, gate_f}, acc_go = {gate_g, gate_o} per batch.
//   weight operand: LDS.128 -> {wi,wf},{wg,wo}  (two natural u64 halves)
//   h operand: h stored DUPLICATED in smem -> LDS.128 {h0,h0,h1,h1}
// Inner iteration: 2x LDS.128 + 4x fma.rn.f32x2 = 6 instr / 8 MACs.

namespace {
constexpr int Bsz = 2048, Tt = 1024, NI = 6, H = 38, HP = 40, Cc = 8;
constexpr int BT = 8;             // batches per block
constexpr int K0 = NI + HP;       // 46 : [x(6) ; h0(40)]
constexpr int K1 = HP + HP;       // 80 : [h0(40) ; h1(40)]
constexpr int NPAIR = BT / 2;     // 4 batch-pairs
constexpr int NTHR = NPAIR * HP;  // 160 threads
constexpr int W0N = K0 * HP * 4;  // 7360 floats
constexpr int W1N = K1 * HP * 4;  // 12800 floats
constexpr int S0N = K0 * BT * 2;  // duplicated state rows, 736 floats
constexpr int S1N = K1 * BT * 2;  // 1280 floats
constexpr int SMEM_FLOATS = W0N + W1N + S0N + S1N;  // 22176 -> 88704 B
}

typedef unsigned long long ull;

__device__ __forceinline__ ull pk2(float a, float b) {
    ull r; asm("mov.b64 %0, {%1, %2};" : "=l"(r) : "f"(a), "f"(b)); return r;
}
__device__ __forceinline__ void fma2(ull &d, ull a, ull b) {
    asm("fma.rn.f32x2 %0, %1, %2, %0;" : "+l"(d) : "l"(a), "l"(b));
}
__device__ __forceinline__ void unpk2(ull v, float &a, float &b) {
    asm("mov.b64 {%0, %1}, %2;" : "=f"(a), "=f"(b) : "l"(v));
}
__device__ __forceinline__ float sigm(float x) {
    return __fdividef(1.0f, 1.0f + __expf(-x));
}
__device__ __forceinline__ float tanh_(float x) {
    // 2/(1+e^{-2x}) - 1 : saturates cleanly to +-1, no NaN at extremes
    return __fdividef(2.0f, 1.0f + __expf(-2.0f * x)) - 1.0f;
}

__global__ void __launch_bounds__(NTHR, 2) lstm_kernel(
    const float* __restrict__ x,    const float* __restrict__ Wih0,
    const float* __restrict__ Whh0, const float* __restrict__ b0,
    const float* __restrict__ Wih1, const float* __restrict__ Whh1,
    const float* __restrict__ b1,   const float* __restrict__ Wc,
    const float* __restrict__ bc,   float* __restrict__ out)
{
    extern __shared__ float sm[];
    float* W0s = sm;            // [k][q][4] = rows {q, H+q, 2H+q, 3H+q} of cat weights
    float* W1s = W0s + W0N;
    float* s0d = W1s + W1N;     // [k][b][2] duplicated state, k in [0,K0)
    float* s1d = s0d + S0N;     // [k][b][2],                 k in [0,K1)

    const int px = threadIdx.x;            // batch pair 0..3
    const int q  = threadIdx.y;            // padded unit 0..39
    const int tid = px + NPAIR * q;
    const int bb0 = blockIdx.x * BT + 2 * px;

    // ---- stage weights into smem (zero-padded to HP units) ----
    for (int idx = tid; idx < W0N; idx += NTHR) {
        int g = idx & 3, qq = (idx >> 2) % HP, k = idx / (4 * HP);
        float v = 0.0f;
        if (qq < H) {
            int row = g * H + qq;
            if (k < NI)             v = Wih0[row * NI + k];
            else if (k - NI < H)    v = Whh0[row * H + (k - NI)];
        }
        W0s[idx] = v;
    }
    for (int idx = tid; idx < W1N; idx += NTHR) {
        int g = idx & 3, qq = (idx >> 2) % HP, k = idx / (4 * HP);
        float v = 0.0f;
        if (qq < H) {
            int row = g * H + qq;
            if (k < HP) { if (k < H) v = Wih1[row * H + k]; }
            else        { int kk = k - HP; if (kk < H) v = Whh1[row * H + kk]; }
        }
        W1s[idx] = v;
    }
    for (int idx = tid; idx < S0N; idx += NTHR) s0d[idx] = 0.0f;
    for (int idx = tid; idx < S1N; idx += NTHR) s1d[idx] = 0.0f;

    // ---- per-thread packed biases ----
    ull bif0, bgo0, bif1, bgo1;
    if (q < H) {
        bif0 = pk2(b0[q], b0[H + q]); bgo0 = pk2(b0[2 * H + q], b0[3 * H + q]);
        bif1 = pk2(b1[q], b1[H + q]); bgo1 = pk2(b1[2 * H + q], b1[3 * H + q]);
    } else {
        bif0 = bgo0 = bif1 = bgo1 = pk2(0.0f, 0.0f);
    }

    // ---- x at t=0 into s0d (duplicated) ----
    if (q < NI) {
        float x0 = x[(size_t)bb0 * Tt * NI + q];
        float x1 = x[(size_t)(bb0 + 1) * Tt * NI + q];
        ulonglong2 xv; xv.x = pk2(x0, x0); xv.y = pk2(x1, x1);
        *(ulonglong2*)(s0d + q * (2 * BT) + 4 * px) = xv;
    }
    __syncthreads();

    float c00 = 0.0f, c01 = 0.0f, c10 = 0.0f, c11 = 0.0f;

    const float* hb0 = s0d + 4 * px;
    const float* hb1 = s1d + 4 * px;
    const float* wq0 = W0s + 4 * q;
    const float* wq1 = W1s + 4 * q;

    for (int t = 0; t < Tt; ++t) {
        // prefetch x_{t+1}
        float xp0 = 0.0f, xp1 = 0.0f;
        if (q < NI && t + 1 < Tt) {
            xp0 = x[(size_t)bb0 * Tt * NI + (t + 1) * NI + q];
            xp1 = x[(size_t)(bb0 + 1) * Tt * NI + (t + 1) * NI + q];
        }

        // ================= layer 0 =================
        float h00, h01;
        {
            ull aif_b0 = bif0, aif_b1 = bif0, ago_b0 = bgo0, ago_b1 = bgo0;
            #pragma unroll
            for (int k = 0; k < K0; ++k) {
                ulonglong2 h2 = *(const ulonglong2*)(hb0 + k * (2 * BT));
                ulonglong2 w2 = *(const ulonglong2*)(wq0 + k * (4 * HP));
                fma2(aif_b0, h2.x, w2.x);
                fma2(aif_b1, h2.y, w2.x);
                fma2(ago_b0, h2.x, w2.y);
                fma2(ago_b1, h2.y, w2.y);
            }
            float gi0, gf0, gg0, go0, gi1, gf1, gg1, go1;
            unpk2(aif_b0, gi0, gf0); unpk2(ago_b0, gg0, go0);
            unpk2(aif_b1, gi1, gf1); unpk2(ago_b1, gg1, go1);
            float i0 = sigm(gi0), f0 = sigm(gf0), g0 = tanh_(gg0), o0 = sigm(go0);
            c00 = f0 * c00 + i0 * g0;
            h00 = o0 * tanh_(c00);
            float i1 = sigm(gi1), f1 = sigm(gf1), g1 = tanh_(gg1), o1 = sigm(go1);
            c01 = f1 * c01 + i1 * g1;
            h01 = o1 * tanh_(c01);
        }

        __syncthreads();   // all layer-0 reads of s0d complete
        {
            ulonglong2 hv; hv.x = pk2(h00, h00); hv.y = pk2(h01, h01);
            *(ulonglong2*)(s0d + (NI + q) * (2 * BT) + 4 * px) = hv;  // for next step's layer 0
            *(ulonglong2*)(s1d + q * (2 * BT) + 4 * px) = hv;         // for this step's layer 1
            if (q < NI && t + 1 < Tt) {
                ulonglong2 xv; xv.x = pk2(xp0, xp0); xv.y = pk2(xp1, xp1);
                *(ulonglong2*)(s0d + q * (2 * BT) + 4 * px) = xv;
            }
        }
        __syncthreads();   // writes visible

        // ================= layer 1 =================
        float h10, h11;
        {
            ull aif_b0 = bif1, aif_b1 = bif1, ago_b0 = bgo1, ago_b1 = bgo1;
            #pragma unroll
            for (int k = 0; k < K1; ++k) {
                ulonglong2 h2 = *(const ulonglong2*)(hb1 + k * (2 * BT));
                ulonglong2 w2 = *(const ulonglong2*)(wq1 + k * (4 * HP));
                fma2(aif_b0, h2.x, w2.x);
                fma2(aif_b1, h2.y, w2.x);
                fma2(ago_b0, h2.x, w2.y);
                fma2(ago_b1, h2.y, w2.y);
            }
            float gi0, gf0, gg0, go0, gi1, gf1, gg1, go1;
            unpk2(aif_b0, gi0, gf0); unpk2(ago_b0, gg0, go0);
            unpk2(aif_b1, gi1, gf1); unpk2(ago_b1, gg1, go1);
            float i0 = sigm(gi0), f0 = sigm(gf0), g0 = tanh_(gg0), o0 = sigm(go0);
            c10 = f0 * c10 + i0 * g0;
            h10 = o0 * tanh_(c10);
            float i1 = sigm(gi1), f1 = sigm(gf1), g1 = tanh_(gg1), o1 = sigm(go1);
            c11 = f1 * c11 + i1 * g1;
            h11 = o1 * tanh_(c11);
        }

        __syncthreads();   // all layer-1 reads of s1d complete
        {
            ulonglong2 hv; hv.x = pk2(h10, h10); hv.y = pk2(h11, h11);
            *(ulonglong2*)(s1d + (HP + q) * (2 * BT) + 4 * px) = hv;
        }
        // h1 writes are consumed only after the next step's two barriers
    }
    __syncthreads();

    // ---- final projection: out[b][c] = bc[c] + sum_k Wc[c][k] * h1_last[b][k] ----
    if (q < Cc) {
        float a0 = bc[q], a1 = bc[q];
        #pragma unroll
        for (int k = 0; k < H; ++k) {
            float w = Wc[q * H + k];
            a0 += w * s1d[(HP + k) * (2 * BT) + 4 * px];
            a1 += w * s1d[(HP + k) * (2 * BT) + 4 * px + 2];
        }
        out[(size_t)bb0 * Cc + q] = a0;
        out[(size_t)(bb0 + 1) * Cc + q] = a1;
    }
}

extern "C" void kernel_launch(void* const* d_in, const int* in_sizes, int n_in,
                              void* d_out, int out_size) {
    const float* x    = (const float*)d_in[0];
    const float* Wih0 = (const float*)d_in[1];
    const float* Whh0 = (const float*)d_in[2];
    const float* b0   = (const float*)d_in[3];
    const float* Wih1 = (const float*)d_in[4];
    const float* Whh1 = (const float*)d_in[5];
    const float* b1   = (const float*)d_in[6];
    const float* Wc   = (const float*)d_in[7];
    const float* bc   = (const float*)d_in[8];

    const int smem_bytes = SMEM_FLOATS * (int)sizeof(float);
    cudaFuncSetAttribute(lstm_kernel, cudaFuncAttributeMaxDynamicSharedMemorySize, smem_bytes);
    lstm_kernel<<<Bsz / BT, dim3(NPAIR, HP, 1), smem_bytes>>>(
        x, Wih0, Whh0, b0, Wih1, Whh1, b1, Wc, bc, (float*)d_out);
}

// round 6
// speedup vs baseline: 1.1408x; 1.1408x over previous
#include <cuda_runtime.h>

// 2-layer LSTM (B=2048, T=1024, I=6, H=38) + projection (C=8), fp32.
// grid=128 persistent blocks, 16 batches/block, 320 threads = 8 batch-pairs x 40 units.
// Thread = (batch-pair px, padded unit q). Batch-pair packed f32x2 FMAs:
//   acc_g = {gate_g_b0, gate_g_b1}  (4 gates = 4 accumulators per pair)
//   h operand: plain state pairs in smem -> LDS.64 {h_b0, h_b1}
//   w operand: weights stored DUPLICATED in smem -> LDS.128 {wi,wi,wf,wf} / {wg,wg,wo,wo}
// Inner iteration: 2x LDS.128 + 1x LDS.64 + 4x fma.rn.f32x2 per 8 MACs.

namespace {
constexpr int Bsz = 2048, Tt = 1024, NI = 6, H = 38, HP = 40, Cc = 8;
constexpr int BT = 16;            // batches per block
constexpr int NPX = BT / 2;       // 8 batch-pairs
constexpr int K0 = NI + HP;       // 46 : [x(6) ; h0(40)]
constexpr int K1 = HP + HP;       // 80 : [h0(40) ; h1(40)]
constexpr int NTHR = NPX * HP;    // 320 threads
constexpr int W0N = K0 * HP * 8;  // dup weights: 14720 floats
constexpr int W1N = K1 * HP * 8;  // 25600 floats
constexpr int S0N = K0 * BT;      // plain state rows: 736 floats
constexpr int S1N = K1 * BT;      // 1280 floats
constexpr int SMEM_FLOATS = W0N + W1N + S0N + S1N;  // 42336 -> 169344 B
}

typedef unsigned long long ull;

__device__ __forceinline__ ull pk2(float a, float b) {
    ull r; asm("mov.b64 %0, {%1, %2};" : "=l"(r) : "f"(a), "f"(b)); return r;
}
__device__ __forceinline__ void fma2(ull &d, ull a, ull b) {
    asm("fma.rn.f32x2 %0, %1, %2, %0;" : "+l"(d) : "l"(a), "l"(b));
}
__device__ __forceinline__ void unpk2(ull v, float &a, float &b) {
    asm("mov.b64 {%0, %1}, %2;" : "=f"(a), "=f"(b) : "l"(v));
}
__device__ __forceinline__ float sigm(float x) {
    return __fdividef(1.0f, 1.0f + __expf(-x));
}
__device__ __forceinline__ float tanh_(float x) {
    return __fdividef(2.0f, 1.0f + __expf(-2.0f * x)) - 1.0f;
}

__global__ void __launch_bounds__(NTHR, 1) lstm_kernel(
    const float* __restrict__ x,    const float* __restrict__ Wih0,
    const float* __restrict__ Whh0, const float* __restrict__ b0,
    const float* __restrict__ Wih1, const float* __restrict__ Whh1,
    const float* __restrict__ b1,   const float* __restrict__ Wc,
    const float* __restrict__ bc,   float* __restrict__ out)
{
    extern __shared__ float sm[];
    float* W0s = sm;            // [k][q][8] = {wi,wi,wf,wf,wg,wg,wo,wo} for unit q
    float* W1s = W0s + W0N;
    float* s0  = W1s + W1N;     // [k][16] plain state, k in [0,K0)
    float* s1  = s0 + S0N;      // [k][16],             k in [0,K1)

    const int px = threadIdx.x;            // batch pair 0..7
    const int q  = threadIdx.y;            // padded unit 0..39
    const int tid = px + NPX * q;
    const int bb0 = blockIdx.x * BT + 2 * px;   // this thread's two batches

    // ---- stage duplicated weights into smem (zero-padded to HP units) ----
    for (int idx = tid; idx < W0N; idx += NTHR) {
        int g = (idx & 7) >> 1, qq = (idx >> 3) % HP, k = idx / (8 * HP);
        float v = 0.0f;
        if (qq < H) {
            int row = g * H + qq;
            if (k < NI)          v = Wih0[row * NI + k];
            else if (k - NI < H) v = Whh0[row * H + (k - NI)];
        }
        W0s[idx] = v;
    }
    for (int idx = tid; idx < W1N; idx += NTHR) {
        int g = (idx & 7) >> 1, qq = (idx >> 3) % HP, k = idx / (8 * HP);
        float v = 0.0f;
        if (qq < H) {
            int row = g * H + qq;
            if (k < HP) { if (k < H) v = Wih1[row * H + k]; }
            else        { int kk = k - HP; if (kk < H) v = Whh1[row * H + kk]; }
        }
        W1s[idx] = v;
    }
    for (int idx = tid; idx < S0N; idx += NTHR) s0[idx] = 0.0f;
    for (int idx = tid; idx < S1N; idx += NTHR) s1[idx] = 0.0f;

    // ---- per-thread packed biases {b,b} ----
    ull bi0, bf0, bg0, bo0, bi1, bf1, bg1, bo1;
    if (q < H) {
        bi0 = pk2(b0[q], b0[q]);             bf0 = pk2(b0[H + q], b0[H + q]);
        bg0 = pk2(b0[2 * H + q], b0[2 * H + q]); bo0 = pk2(b0[3 * H + q], b0[3 * H + q]);
        bi1 = pk2(b1[q], b1[q]);             bf1 = pk2(b1[H + q], b1[H + q]);
        bg1 = pk2(b1[2 * H + q], b1[2 * H + q]); bo1 = pk2(b1[3 * H + q], b1[3 * H + q]);
    } else {
        bi0 = bf0 = bg0 = bo0 = bi1 = bf1 = bg1 = bo1 = pk2(0.0f, 0.0f);
    }

    // ---- x at t=0 into s0 ----
    if (q < NI) {
        float x0 = x[(size_t)bb0 * Tt * NI + q];
        float x1 = x[(size_t)(bb0 + 1) * Tt * NI + q];
        *(float2*)(s0 + q * BT + 2 * px) = make_float2(x0, x1);
    }
    __syncthreads();

    float c00 = 0.0f, c01 = 0.0f, c10 = 0.0f, c11 = 0.0f;

    const float* hb0 = s0 + 2 * px;
    const float* hb1 = s1 + 2 * px;
    const float* wq0 = W0s + 8 * q;
    const float* wq1 = W1s + 8 * q;

    for (int t = 0; t < Tt; ++t) {
        // prefetch x_{t+1}
        float xp0 = 0.0f, xp1 = 0.0f;
        if (q < NI && t + 1 < Tt) {
            xp0 = x[(size_t)bb0 * Tt * NI + (t + 1) * NI + q];
            xp1 = x[(size_t)(bb0 + 1) * Tt * NI + (t + 1) * NI + q];
        }

        // ================= layer 0 =================
        float h00, h01;
        {
            ull ai = bi0, af = bf0, ag = bg0, ao = bo0;
            #pragma unroll
            for (int k = 0; k < K0; ++k) {
                ull hv = *(const ull*)(hb0 + k * BT);                    // {h_b0, h_b1}
                ulonglong2 wif = *(const ulonglong2*)(wq0 + k * (8 * HP));     // {wi,wi},{wf,wf}
                ulonglong2 wgo = *(const ulonglong2*)(wq0 + k * (8 * HP) + 4); // {wg,wg},{wo,wo}
                fma2(ai, hv, wif.x);
                fma2(af, hv, wif.y);
                fma2(ag, hv, wgo.x);
                fma2(ao, hv, wgo.y);
            }
            float gi0, gi1, gf0, gf1, gg0, gg1, go0, go1;
            unpk2(ai, gi0, gi1); unpk2(af, gf0, gf1);
            unpk2(ag, gg0, gg1); unpk2(ao, go0, go1);
            float i0 = sigm(gi0), f0 = sigm(gf0), g0 = tanh_(gg0), o0 = sigm(go0);
            c00 = f0 * c00 + i0 * g0;
            h00 = o0 * tanh_(c00);
            float i1 = sigm(gi1), f1 = sigm(gf1), g1 = tanh_(gg1), o1 = sigm(go1);
            c01 = f1 * c01 + i1 * g1;
            h01 = o1 * tanh_(c01);
        }

        __syncthreads();   // all layer-0 reads of s0 complete
        {
            float2 hv = make_float2(h00, h01);
            *(float2*)(s0 + (NI + q) * BT + 2 * px) = hv;   // next step's layer 0
            *(float2*)(s1 + q * BT + 2 * px) = hv;          // this step's layer 1
            if (q < NI && t + 1 < Tt)
                *(float2*)(s0 + q * BT + 2 * px) = make_float2(xp0, xp1);
        }
        __syncthreads();   // writes visible

        // ================= layer 1 =================
        float h10, h11;
        {
            ull ai = bi1, af = bf1, ag = bg1, ao = bo1;
            #pragma unroll
            for (int k = 0; k < K1; ++k) {
                ull hv = *(const ull*)(hb1 + k * BT);
                ulonglong2 wif = *(const ulonglong2*)(wq1 + k * (8 * HP));
                ulonglong2 wgo = *(const ulonglong2*)(wq1 + k * (8 * HP) + 4);
                fma2(ai, hv, wif.x);
                fma2(af, hv, wif.y);
                fma2(ag, hv, wgo.x);
                fma2(ao, hv, wgo.y);
            }
            float gi0, gi1, gf0, gf1, gg0, gg1, go0, go1;
            unpk2(ai, gi0, gi1); unpk2(af, gf0, gf1);
            unpk2(ag, gg0, gg1); unpk2(ao, go0, go1);
            float i0 = sigm(gi0), f0 = sigm(gf0), g0 = tanh_(gg0), o0 = sigm(go0);
            c10 = f0 * c10 + i0 * g0;
            h10 = o0 * tanh_(c10);
            float i1 = sigm(gi1), f1 = sigm(gf1), g1 = tanh_(gg1), o1 = sigm(go1);
            c11 = f1 * c11 + i1 * g1;
            h11 = o1 * tanh_(c11);
        }

        __syncthreads();   // all layer-1 reads of s1 complete
        *(float2*)(s1 + (HP + q) * BT + 2 * px) = make_float2(h10, h11);
        // consumed only after next step's two barriers (disjoint region)
    }
    __syncthreads();

    // ---- final projection: out[b][c] = bc[c] + sum_k Wc[c][k] * h1_last[b][k] ----
    if (q < Cc) {
        float a0 = bc[q], a1 = bc[q];
        #pragma unroll
        for (int k = 0; k < H; ++k) {
            float w = Wc[q * H + k];
            float2 hv = *(const float2*)(s1 + (HP + k) * BT + 2 * px);
            a0 += w * hv.x;
            a1 += w * hv.y;
        }
        out[(size_t)bb0 * Cc + q] = a0;
        out[(size_t)(bb0 + 1) * Cc + q] = a1;
    }
}

extern "C" void kernel_launch(void* const* d_in, const int* in_sizes, int n_in,
                              void* d_out, int out_size) {
    const float* x    = (const float*)d_in[0];
    const float* Wih0 = (const float*)d_in[1];
    const float* Whh0 = (const float*)d_in[2];
    const float* b0   = (const float*)d_in[3];
    const float* Wih1 = (const float*)d_in[4];
    const float* Whh1 = (const float*)d_in[5];
    const float* b1   = (const float*)d_in[6];
    const float* Wc   = (const float*)d_in[7];
    const float* bc   = (const float*)d_in[8];

    const int smem_bytes = SMEM_FLOATS * (int)sizeof(float);
    cudaFuncSetAttribute(lstm_kernel, cudaFuncAttributeMaxDynamicSharedMemorySize, smem_bytes);
    lstm_kernel<<<Bsz / BT, dim3(NPX, HP, 1), smem_bytes>>>(
        x, Wih0, Whh0, b0, Wih1, Whh1, b1, Wc, bc, (float*)d_out);
}

// round 7
// speedup vs baseline: 1.2349x; 1.0825x over previous
#include <cuda_runtime.h>

// 2-layer LSTM (B=2048, T=1024, I=6, H=38) + projection (C=8), fp32.
// grid=128 persistent blocks, 16 batches/block, 160 threads = 4 px x 40 units.
// Thread = (px, padded unit q), owns 4 batches. Batch-pair packed f32x2:
//   8 accumulators: {gate}x{b01,b23}. Per k:
//     1x LDS.128 h        -> {h0,h1},{h2,h3}           (broadcast across q)
//     1x LDS.128 Wif[k][q] -> {wi,wi},{wf,wf}          (128B/warp row, conflict-free)
//     1x LDS.128 Wgo[k][q] -> {wg,wg},{wo,wo}
//     8x fma.rn.f32x2      => 16 MACs
// Weight arrays are split (if / go) so each warp LDS covers one aligned 128B row.

namespace {
constexpr int Bsz = 2048, Tt = 1024, NI = 6, H = 38, HP = 40, Cc = 8;
constexpr int BT = 16;            // batches per block
constexpr int NPX = 4;            // threads in px dim (4 batches each)
constexpr int K0 = NI + HP;       // 46 : [x(6) ; h0(40)]
constexpr int K1 = HP + HP;       // 80 : [h0(40) ; h1(40)]
constexpr int NTHR = NPX * HP;    // 160 threads
constexpr int W0G = K0 * HP * 4;  // one gate-pair array, layer0: 7360 floats
constexpr int W1G = K1 * HP * 4;  // 12800 floats
constexpr int S0N = K0 * BT;      // 736
constexpr int S1N = K1 * BT;      // 1280
constexpr int SMEM_FLOATS = 2 * W0G + 2 * W1G + S0N + S1N;  // 42336 -> 169344 B
}

typedef unsigned long long ull;

__device__ __forceinline__ ull pk2(float a, float b) {
    ull r; asm("mov.b64 %0, {%1, %2};" : "=l"(r) : "f"(a), "f"(b)); return r;
}
__device__ __forceinline__ void fma2(ull &d, ull a, ull b) {
    asm("fma.rn.f32x2 %0, %1, %2, %0;" : "+l"(d) : "l"(a), "l"(b));
}
__device__ __forceinline__ void unpk2(ull v, float &a, float &b) {
    asm("mov.b64 {%0, %1}, %2;" : "=f"(a), "=f"(b) : "l"(v));
}
__device__ __forceinline__ float sigm(float x) {
    return __fdividef(1.0f, 1.0f + __expf(-x));
}
__device__ __forceinline__ float tanh_(float x) {
    return __fdividef(2.0f, 1.0f + __expf(-2.0f * x)) - 1.0f;
}

__global__ void __launch_bounds__(NTHR, 1) lstm_kernel(
    const float* __restrict__ x,    const float* __restrict__ Wih0,
    const float* __restrict__ Whh0, const float* __restrict__ b0,
    const float* __restrict__ Wih1, const float* __restrict__ Whh1,
    const float* __restrict__ b1,   const float* __restrict__ Wc,
    const float* __restrict__ bc,   float* __restrict__ out)
{
    extern __shared__ float sm[];
    float* W0if = sm;               // [k][q][4] = {wi,wi,wf,wf}
    float* W0go = W0if + W0G;       // [k][q][4] = {wg,wg,wo,wo}
    float* W1if = W0go + W0G;
    float* W1go = W1if + W1G;
    float* s0   = W1go + W1G;       // [k][16] plain state, k in [0,K0)
    float* s1   = s0 + S0N;         // [k][16],             k in [0,K1)

    const int px = threadIdx.x;                 // 0..3, 4 batches each
    const int q  = threadIdx.y;                 // padded unit 0..39
    const int tid = px + NPX * q;
    const int bb0 = blockIdx.x * BT + 4 * px;   // first of this thread's 4 batches

    // ---- stage weights (duplicated pairs, zero-padded units) ----
    for (int idx = tid; idx < W0G; idx += NTHR) {
        int j = idx & 3, qq = (idx >> 2) % HP, k = idx / (4 * HP);
        int g = j >> 1;                          // 0:i 1:f
        float vif = 0.0f, vgo = 0.0f;
        if (qq < H) {
            int rif = g * H + qq, rgo = (g + 2) * H + qq;
            if (k < NI) { vif = Wih0[rif * NI + k];        vgo = Wih0[rgo * NI + k]; }
            else if (k - NI < H) { vif = Whh0[rif * H + (k - NI)]; vgo = Whh0[rgo * H + (k - NI)]; }
        }
        W0if[idx] = vif;
        W0go[idx] = vgo;
    }
    for (int idx = tid; idx < W1G; idx += NTHR) {
        int j = idx & 3, qq = (idx >> 2) % HP, k = idx / (4 * HP);
        int g = j >> 1;
        float vif = 0.0f, vgo = 0.0f;
        if (qq < H) {
            int rif = g * H + qq, rgo = (g + 2) * H + qq;
            if (k < HP) {
                if (k < H) { vif = Wih1[rif * H + k]; vgo = Wih1[rgo * H + k]; }
            } else {
                int kk = k - HP;
                if (kk < H) { vif = Whh1[rif * H + kk]; vgo = Whh1[rgo * H + kk]; }
            }
        }
        W1if[idx] = vif;
        W1go[idx] = vgo;
    }
    for (int idx = tid; idx < S0N; idx += NTHR) s0[idx] = 0.0f;
    for (int idx = tid; idx < S1N; idx += NTHR) s1[idx] = 0.0f;

    // ---- per-thread packed biases {b,b} ----
    ull bi0, bf0, bg0, bo0, bi1, bf1, bg1, bo1;
    if (q < H) {
        bi0 = pk2(b0[q], b0[q]);                 bf0 = pk2(b0[H + q], b0[H + q]);
        bg0 = pk2(b0[2 * H + q], b0[2 * H + q]); bo0 = pk2(b0[3 * H + q], b0[3 * H + q]);
        bi1 = pk2(b1[q], b1[q]);                 bf1 = pk2(b1[H + q], b1[H + q]);
        bg1 = pk2(b1[2 * H + q], b1[2 * H + q]); bo1 = pk2(b1[3 * H + q], b1[3 * H + q]);
    } else {
        bi0 = bf0 = bg0 = bo0 = bi1 = bf1 = bg1 = bo1 = pk2(0.0f, 0.0f);
    }

    // ---- x at t=0 into s0 ----
    if (q < NI) {
        float4 xv;
        xv.x = x[(size_t)(bb0 + 0) * Tt * NI + q];
        xv.y = x[(size_t)(bb0 + 1) * Tt * NI + q];
        xv.z = x[(size_t)(bb0 + 2) * Tt * NI + q];
        xv.w = x[(size_t)(bb0 + 3) * Tt * NI + q];
        *(float4*)(s0 + q * BT + 4 * px) = xv;
    }
    __syncthreads();

    float c0[4] = {0.f, 0.f, 0.f, 0.f};   // layer0 cell state, 4 batches
    float c1[4] = {0.f, 0.f, 0.f, 0.f};   // layer1

    const float* hb0 = s0 + 4 * px;
    const float* hb1 = s1 + 4 * px;
    const float* wq0if = W0if + 4 * q;
    const float* wq0go = W0go + 4 * q;
    const float* wq1if = W1if + 4 * q;
    const float* wq1go = W1go + 4 * q;

    for (int t = 0; t < Tt; ++t) {
        // prefetch x_{t+1} (covered by layer-0 compute latency)
        float xp0 = 0.f, xp1 = 0.f, xp2 = 0.f, xp3 = 0.f;
        if (q < NI && t + 1 < Tt) {
            size_t o = (size_t)(t + 1) * NI + q;
            xp0 = x[(size_t)(bb0 + 0) * Tt * NI + o];
            xp1 = x[(size_t)(bb0 + 1) * Tt * NI + o];
            xp2 = x[(size_t)(bb0 + 2) * Tt * NI + o];
            xp3 = x[(size_t)(bb0 + 3) * Tt * NI + o];
        }

        // ================= layer 0 =================
        float h0r[4];
        {
            ull ai01 = bi0, ai23 = bi0, af01 = bf0, af23 = bf0;
            ull ag01 = bg0, ag23 = bg0, ao01 = bo0, ao23 = bo0;
            #pragma unroll
            for (int k = 0; k < K0; ++k) {
                ulonglong2 hv  = *(const ulonglong2*)(hb0 + k * BT);          // {h0,h1},{h2,h3}
                ulonglong2 wif = *(const ulonglong2*)(wq0if + k * (4 * HP));  // {wi,wi},{wf,wf}
                ulonglong2 wgo = *(const ulonglong2*)(wq0go + k * (4 * HP));  // {wg,wg},{wo,wo}
                fma2(ai01, hv.x, wif.x); fma2(ai23, hv.y, wif.x);
                fma2(af01, hv.x, wif.y); fma2(af23, hv.y, wif.y);
                fma2(ag01, hv.x, wgo.x); fma2(ag23, hv.y, wgo.x);
                fma2(ao01, hv.x, wgo.y); fma2(ao23, hv.y, wgo.y);
            }
            float gi[4], gf[4], gg[4], go[4];
            unpk2(ai01, gi[0], gi[1]); unpk2(ai23, gi[2], gi[3]);
            unpk2(af01, gf[0], gf[1]); unpk2(af23, gf[2], gf[3]);
            unpk2(ag01, gg[0], gg[1]); unpk2(ag23, gg[2], gg[3]);
            unpk2(ao01, go[0], go[1]); unpk2(ao23, go[2], go[3]);
            #pragma unroll
            for (int j = 0; j < 4; ++j) {
                float i = sigm(gi[j]), f = sigm(gf[j]), g = tanh_(gg[j]), o = sigm(go[j]);
                c0[j] = f * c0[j] + i * g;
                h0r[j] = o * tanh_(c0[j]);
            }
        }

        __syncthreads();   // all layer-0 reads of s0 complete
        {
            float4 hv = make_float4(h0r[0], h0r[1], h0r[2], h0r[3]);
            *(float4*)(s0 + (NI + q) * BT + 4 * px) = hv;   // next step's layer 0
            *(float4*)(s1 + q * BT + 4 * px) = hv;          // this step's layer 1
            if (q < NI && t + 1 < Tt)
                *(float4*)(s0 + q * BT + 4 * px) = make_float4(xp0, xp1, xp2, xp3);
        }
        __syncthreads();   // writes visible

        // ================= layer 1 =================
        float h1r[4];
        {
            ull ai01 = bi1, ai23 = bi1, af01 = bf1, af23 = bf1;
            ull ag01 = bg1, ag23 = bg1, ao01 = bo1, ao23 = bo1;
            #pragma unroll
            for (int k = 0; k < K1; ++k) {
                ulonglong2 hv  = *(const ulonglong2*)(hb1 + k * BT);
                ulonglong2 wif = *(const ulonglong2*)(wq1if + k * (4 * HP));
                ulonglong2 wgo = *(const ulonglong2*)(wq1go + k * (4 * HP));
                fma2(ai01, hv.x, wif.x); fma2(ai23, hv.y, wif.x);
                fma2(af01, hv.x, wif.y); fma2(af23, hv.y, wif.y);
                fma2(ag01, hv.x, wgo.x); fma2(ag23, hv.y, wgo.x);
                fma2(ao01, hv.x, wgo.y); fma2(ao23, hv.y, wgo.y);
            }
            float gi[4], gf[4], gg[4], go[4];
            unpk2(ai01, gi[0], gi[1]); unpk2(ai23, gi[2], gi[3]);
            unpk2(af01, gf[0], gf[1]); unpk2(af23, gf[2], gf[3]);
            unpk2(ag01, gg[0], gg[1]); unpk2(ag23, gg[2], gg[3]);
            unpk2(ao01, go[0], go[1]); unpk2(ao23, go[2], go[3]);
            #pragma unroll
            for (int j = 0; j < 4; ++j) {
                float i = sigm(gi[j]), f = sigm(gf[j]), g = tanh_(gg[j]), o = sigm(go[j]);
                c1[j] = f * c1[j] + i * g;
                h1r[j] = o * tanh_(c1[j]);
            }
        }

        __syncthreads();   // all layer-1 reads of s1 complete
        *(float4*)(s1 + (HP + q) * BT + 4 * px) = make_float4(h1r[0], h1r[1], h1r[2], h1r[3]);
        // consumed only after next step's two barriers (disjoint rows)
    }
    __syncthreads();

    // ---- final projection: out[b][c] = bc[c] + sum_k Wc[c][k] * h1_last[b][k] ----
    if (q < Cc) {
        float a0 = bc[q], a1 = a0, a2 = a0, a3 = a0;
        #pragma unroll
        for (int k = 0; k < H; ++k) {
            float w = Wc[q * H + k];
            float4 hv = *(const float4*)(s1 + (HP + k) * BT + 4 * px);
            a0 += w * hv.x; a1 += w * hv.y; a2 += w * hv.z; a3 += w * hv.w;
        }
        out[(size_t)(bb0 + 0) * Cc + q] = a0;
        out[(size_t)(bb0 + 1) * Cc + q] = a1;
        out[(size_t)(bb0 + 2) * Cc + q] = a2;
        out[(size_t)(bb0 + 3) * Cc + q] = a3;
    }
}

extern "C" void kernel_launch(void* const* d_in, const int* in_sizes, int n_in,
                              void* d_out, int out_size) {
    const float* x    = (const float*)d_in[0];
    const float* Wih0 = (const float*)d_in[1];
    const float* Whh0 = (const float*)d_in[2];
    const float* b0   = (const float*)d_in[3];
    const float* Wih1 = (const float*)d_in[4];
    const float* Whh1 = (const float*)d_in[5];
    const float* b1   = (const float*)d_in[6];
    const float* Wc   = (const float*)d_in[7];
    const float* bc   = (const float*)d_in[8];

    const int smem_bytes = SMEM_FLOATS * (int)sizeof(float);
    cudaFuncSetAttribute(lstm_kernel, cudaFuncAttributeMaxDynamicSharedMemorySize, smem_bytes);
    lstm_kernel<<<Bsz / BT, dim3(NPX, HP, 1), smem_bytes>>>(
        x, Wih0, Whh0, b0, Wih1, Whh1, b1, Wc, bc, (float*)d_out);
}

// round 8
// speedup vs baseline: 1.5974x; 1.2936x over previous
#include <cuda_runtime.h>

// 2-layer LSTM (B=2048, T=1024, I=6, H=38) + projection (C=8), fp32.
// grid=128 persistent blocks, 16 batches/block, 320 threads = 8 px x 40 units.
// Thread = (px, q), owns batch pair. Per-batch gate-pair f32x2 accumulators:
//   acc_if_b = {gate_i, gate_f},  acc_go_b = {gate_g, gate_o}
// Per k:
//   1x LDS.128  W[k][q]  -> {wi,wf},{wg,wo}   (non-duplicated, 2 wavefronts)
//   1x LDS.64   h[k]     -> {h_b0, h_b1}      (non-duplicated, 1 wavefront)
//   2x reg splat {h,h}   (alu pipe, nearly idle)
//   4x fma.rn.f32x2      => 8 MACs
// 10 warps/SM for latency hiding; SMEM 88.7 KB.

namespace {
constexpr int Bsz = 2048, Tt = 1024, NI = 6, H = 38, HP = 40, Cc = 8;
constexpr int BT = 16;            // batches per block
constexpr int NPX = 8;            // batch-pairs (threads in x)
constexpr int K0 = NI + HP;       // 46 : [x(6) ; h0(40)]
constexpr int K1 = HP + HP;       // 80 : [h0(40) ; h1(40)]
constexpr int NTHR = NPX * HP;    // 320 threads
constexpr int W0N = K0 * HP * 4;  // 7360 floats  {wi,wf,wg,wo} per (k,q)
constexpr int W1N = K1 * HP * 4;  // 12800 floats
constexpr int S0N = K0 * BT;      // 736  plain state rows
constexpr int S1N = K1 * BT;      // 1280
constexpr int SMEM_FLOATS = W0N + W1N + S0N + S1N;  // 22176 -> 88704 B
}

typedef unsigned long long ull;

__device__ __forceinline__ ull pk2(float a, float b) {
    ull r; asm("mov.b64 %0, {%1, %2};" : "=l"(r) : "f"(a), "f"(b)); return r;
}
__device__ __forceinline__ ull splat(float v) {
    ull r; asm("mov.b64 %0, {%1, %1};" : "=l"(r) : "f"(v)); return r;
}
__device__ __forceinline__ void fma2(ull &d, ull a, ull b) {
    asm("fma.rn.f32x2 %0, %1, %2, %0;" : "+l"(d) : "l"(a), "l"(b));
}
__device__ __forceinline__ void unpk2(ull v, float &a, float &b) {
    asm("mov.b64 {%0, %1}, %2;" : "=f"(a), "=f"(b) : "l"(v));
}
__device__ __forceinline__ float sigm(float x) {
    return __fdividef(1.0f, 1.0f + __expf(-x));
}
__device__ __forceinline__ float tanh_(float x) {
    return __fdividef(2.0f, 1.0f + __expf(-2.0f * x)) - 1.0f;
}

__global__ void __launch_bounds__(NTHR, 1) lstm_kernel(
    const float* __restrict__ x,    const float* __restrict__ Wih0,
    const float* __restrict__ Whh0, const float* __restrict__ b0,
    const float* __restrict__ Wih1, const float* __restrict__ Whh1,
    const float* __restrict__ b1,   const float* __restrict__ Wc,
    const float* __restrict__ bc,   float* __restrict__ out)
{
    extern __shared__ float sm[];
    float* W0s = sm;            // [k][q][4] = {wi,wf,wg,wo}
    float* W1s = W0s + W0N;
    float* s0  = W1s + W1N;     // [k][16] plain state, k in [0,K0)
    float* s1  = s0 + S0N;      // [k][16],             k in [0,K1)

    const int px = threadIdx.x;                 // 0..7
    const int q  = threadIdx.y;                 // 0..39
    const int tid = px + NPX * q;
    const int bb0 = blockIdx.x * BT + 2 * px;   // this thread's two batches

    // ---- stage weights {wi,wf,wg,wo} per (k,q), zero-padded units ----
    for (int idx = tid; idx < W0N; idx += NTHR) {
        int g = idx & 3, qq = (idx >> 2) % HP, k = idx / (4 * HP);
        float v = 0.0f;
        if (qq < H) {
            int row = g * H + qq;
            if (k < NI)          v = Wih0[row * NI + k];
            else if (k - NI < H) v = Whh0[row * H + (k - NI)];
        }
        W0s[idx] = v;
    }
    for (int idx = tid; idx < W1N; idx += NTHR) {
        int g = idx & 3, qq = (idx >> 2) % HP, k = idx / (4 * HP);
        float v = 0.0f;
        if (qq < H) {
            int row = g * H + qq;
            if (k < HP) { if (k < H) v = Wih1[row * H + k]; }
            else        { int kk = k - HP; if (kk < H) v = Whh1[row * H + kk]; }
        }
        W1s[idx] = v;
    }
    for (int idx = tid; idx < S0N; idx += NTHR) s0[idx] = 0.0f;
    for (int idx = tid; idx < S1N; idx += NTHR) s1[idx] = 0.0f;

    // ---- per-thread packed biases (natural gate pairs) ----
    ull bif0, bgo0, bif1, bgo1;
    if (q < H) {
        bif0 = pk2(b0[q], b0[H + q]); bgo0 = pk2(b0[2 * H + q], b0[3 * H + q]);
        bif1 = pk2(b1[q], b1[H + q]); bgo1 = pk2(b1[2 * H + q], b1[3 * H + q]);
    } else {
        bif0 = bgo0 = bif1 = bgo1 = pk2(0.0f, 0.0f);
    }

    // ---- x at t=0 into s0 ----
    if (q < NI) {
        float x0 = x[(size_t)bb0 * Tt * NI + q];
        float x1 = x[(size_t)(bb0 + 1) * Tt * NI + q];
        *(float2*)(s0 + q * BT + 2 * px) = make_float2(x0, x1);
    }
    __syncthreads();

    float c00 = 0.0f, c01 = 0.0f, c10 = 0.0f, c11 = 0.0f;

    const float* hb0 = s0 + 2 * px;
    const float* hb1 = s1 + 2 * px;
    const float* wq0 = W0s + 4 * q;
    const float* wq1 = W1s + 4 * q;

    for (int t = 0; t < Tt; ++t) {
        // prefetch x_{t+1} (hidden under layer-0 compute)
        float xp0 = 0.0f, xp1 = 0.0f;
        if (q < NI && t + 1 < Tt) {
            size_t o = (size_t)(t + 1) * NI + q;
            xp0 = x[(size_t)bb0 * Tt * NI + o];
            xp1 = x[(size_t)(bb0 + 1) * Tt * NI + o];
        }

        // ================= layer 0 =================
        float h00, h01;
        {
            ull aif0 = bif0, ago0 = bgo0, aif1 = bif0, ago1 = bgo0;
            #pragma unroll
            for (int k = 0; k < K0; ++k) {
                float2 hp = *(const float2*)(hb0 + k * BT);             // {h_b0, h_b1}
                ulonglong2 w = *(const ulonglong2*)(wq0 + k * (4 * HP)); // {wi,wf},{wg,wo}
                ull h0s = splat(hp.x), h1s = splat(hp.y);
                fma2(aif0, h0s, w.x); fma2(ago0, h0s, w.y);
                fma2(aif1, h1s, w.x); fma2(ago1, h1s, w.y);
            }
            float gi0, gf0, gg0, go0, gi1, gf1, gg1, go1;
            unpk2(aif0, gi0, gf0); unpk2(ago0, gg0, go0);
            unpk2(aif1, gi1, gf1); unpk2(ago1, gg1, go1);
            float i0 = sigm(gi0), f0 = sigm(gf0), g0 = tanh_(gg0), o0 = sigm(go0);
            c00 = f0 * c00 + i0 * g0;
            h00 = o0 * tanh_(c00);
            float i1 = sigm(gi1), f1 = sigm(gf1), g1 = tanh_(gg1), o1 = sigm(go1);
            c01 = f1 * c01 + i1 * g1;
            h01 = o1 * tanh_(c01);
        }

        __syncthreads();   // all layer-0 reads of s0 complete
        {
            float2 hv = make_float2(h00, h01);
            *(float2*)(s0 + (NI + q) * BT + 2 * px) = hv;   // next step's layer 0
            *(float2*)(s1 + q * BT + 2 * px) = hv;          // this step's layer 1
            if (q < NI && t + 1 < Tt)
                *(float2*)(s0 + q * BT + 2 * px) = make_float2(xp0, xp1);
        }
        __syncthreads();   // writes visible

        // ================= layer 1 =================
        float h10, h11;
        {
            ull aif0 = bif1, ago0 = bgo1, aif1 = bif1, ago1 = bgo1;
            #pragma unroll
            for (int k = 0; k < K1; ++k) {
                float2 hp = *(const float2*)(hb1 + k * BT);
                ulonglong2 w = *(const ulonglong2*)(wq1 + k * (4 * HP));
                ull h0s = splat(hp.x), h1s = splat(hp.y);
                fma2(aif0, h0s, w.x); fma2(ago0, h0s, w.y);
                fma2(aif1, h1s, w.x); fma2(ago1, h1s, w.y);
            }
            float gi0, gf0, gg0, go0, gi1, gf1, gg1, go1;
            unpk2(aif0, gi0, gf0); unpk2(ago0, gg0, go0);
            unpk2(aif1, gi1, gf1); unpk2(ago1, gg1, go1);
            float i0 = sigm(gi0), f0 = sigm(gf0), g0 = tanh_(gg0), o0 = sigm(go0);
            c10 = f0 * c10 + i0 * g0;
            h10 = o0 * tanh_(c10);
            float i1 = sigm(gi1), f1 = sigm(gf1), g1 = tanh_(gg1), o1 = sigm(go1);
            c11 = f1 * c11 + i1 * g1;
            h11 = o1 * tanh_(c11);
        }

        __syncthreads();   // all layer-1 reads of s1 complete
        *(float2*)(s1 + (HP + q) * BT + 2 * px) = make_float2(h10, h11);
        // consumed only after next step's two barriers (disjoint rows)
    }
    __syncthreads();

    // ---- final projection: out[b][c] = bc[c] + sum_k Wc[c][k] * h1_last[b][k] ----
    if (q < Cc) {
        float a0 = bc[q], a1 = a0;
        #pragma unroll
        for (int k = 0; k < H; ++k) {
            float w = Wc[q * H + k];
            float2 hv = *(const float2*)(s1 + (HP + k) * BT + 2 * px);
            a0 += w * hv.x;
            a1 += w * hv.y;
        }
        out[(size_t)bb0 * Cc + q] = a0;
        out[(size_t)(bb0 + 1) * Cc + q] = a1;
    }
}

extern "C" void kernel_launch(void* const* d_in, const int* in_sizes, int n_in,
                              void* d_out, int out_size) {
    const float* x    = (const float*)d_in[0];
    const float* Wih0 = (const float*)d_in[1];
    const float* Whh0 = (const float*)d_in[2];
    const float* b0   = (const float*)d_in[3];
    const float* Wih1 = (const float*)d_in[4];
    const float* Whh1 = (const float*)d_in[5];
    const float* b1   = (const float*)d_in[6];
    const float* Wc   = (const float*)d_in[7];
    const float* bc   = (const float*)d_in[8];

    const int smem_bytes = SMEM_FLOATS * (int)sizeof(float);
    cudaFuncSetAttribute(lstm_kernel, cudaFuncAttributeMaxDynamicSharedMemorySize, smem_bytes);
    lstm_kernel<<<Bsz / BT, dim3(NPX, HP, 1), smem_bytes>>>(
        x, Wih0, Whh0, b0, Wih1, Whh1, b1, Wc, bc, (float*)d_out);
}

// round 9
// speedup vs baseline: 1.8009x; 1.1274x over previous
#include <cuda_runtime.h>

// 2-layer LSTM (B=2048, T=1024, I=6, H=38) + projection (C=8), fp32.
// grid=128 persistent blocks, 16 batches/block, 320 threads.
// LAYER-PIPELINED warp groups:
//   group A (threads 0..159,   5 warps): layer 0, step t
//   group B (threads 160..319, 5 warps): layer 1, step t-1
//   h0 handed off through double-buffered SMEM rows; 2 barriers/step.
// Thread = (px 0..3, q 0..39), owns 4 batches. Per k:
//   1x LDS.128 W[k][q] -> {wi,wf},{wg,wo}
//   1x LDS.128 h       -> {h_b0..h_b3}
//   4x reg splat {h,h} (ALU) + 8x fma.rn.f32x2 => 16 MACs / 4 L1-cycles.

namespace {
constexpr int Bsz = 2048, Tt = 1024, NI = 6, H = 38, HP = 40, Cc = 8;
constexpr int BT = 16;             // batches per block
constexpr int NPX = 4;             // 4 batches per thread
constexpr int GRP = NPX * HP;      // 160 threads per group
constexpr int NTHR = 2 * GRP;      // 320
constexpr int WAN = (NI + HP) * HP * 4;   // 7360 floats
constexpr int WBN = (HP + HP) * HP * 4;   // 12800 floats
// state rows of 16 floats:
// s0: x rows [0..NI), h0 double-buffer [NI .. NI+2*HP)
// s1: h0 double-buffer [0..2*HP), h1 double-buffer [2*HP..4*HP)
constexpr int S0ROWS = NI + 2 * HP;   // 86
constexpr int S1ROWS = 4 * HP;        // 160
constexpr int S0N = S0ROWS * BT;      // 1376
constexpr int S1N = S1ROWS * BT;      // 2560
constexpr int SMEM_FLOATS = WAN + WBN + S0N + S1N;  // 24096 -> 96384 B
}

typedef unsigned long long ull;

__device__ __forceinline__ ull pk2(float a, float b) {
    ull r; asm("mov.b64 %0, {%1, %2};" : "=l"(r) : "f"(a), "f"(b)); return r;
}
__device__ __forceinline__ ull splat(float v) {
    ull r; asm("mov.b64 %0, {%1, %1};" : "=l"(r) : "f"(v)); return r;
}
__device__ __forceinline__ void fma2(ull &d, ull a, ull b) {
    asm("fma.rn.f32x2 %0, %1, %2, %0;" : "+l"(d) : "l"(a), "l"(b));
}
__device__ __forceinline__ void unpk2(ull v, float &a, float &b) {
    asm("mov.b64 {%0, %1}, %2;" : "=f"(a), "=f"(b) : "l"(v));
}
__device__ __forceinline__ float sigm(float x) {
    return __fdividef(1.0f, 1.0f + __expf(-x));
}
__device__ __forceinline__ float tanh_(float x) {
    return __fdividef(2.0f, 1.0f + __expf(-2.0f * x)) - 1.0f;
}

__global__ void __launch_bounds__(NTHR, 1) lstm_kernel(
    const float* __restrict__ x,    const float* __restrict__ Wih0,
    const float* __restrict__ Whh0, const float* __restrict__ b0,
    const float* __restrict__ Wih1, const float* __restrict__ Whh1,
    const float* __restrict__ b1,   const float* __restrict__ Wc,
    const float* __restrict__ bc,   float* __restrict__ out)
{
    extern __shared__ float sm[];
    float* WA = sm;             // [k][q][4]={wi,wf,wg,wo}, k: 0..5 x, 6..45 h0
    float* WB = WA + WAN;       // [k][q][4],               k: 0..39 h0, 40..79 h1
    float* s0 = WB + WBN;       // rows of 16 floats
    float* s1 = s0 + S0N;

    const int tid = threadIdx.x;
    const int grp = tid >= GRP;          // 0 = layer0 group, 1 = layer1 group
    const int lt  = tid - grp * GRP;
    const int px  = lt & 3;              // 0..3, 4 batches each
    const int q   = lt >> 2;             // 0..39
    const int bb0 = blockIdx.x * BT + 4 * px;

    // ---- stage weights (zero-padded units / k rows) ----
    for (int idx = tid; idx < WAN; idx += NTHR) {
        int g = idx & 3, qq = (idx >> 2) % HP, k = idx / (4 * HP);
        float v = 0.0f;
        if (qq < H) {
            int row = g * H + qq;
            if (k < NI)          v = Wih0[row * NI + k];
            else { int kk = k - NI; if (kk < H) v = Whh0[row * H + kk]; }
        }
        WA[idx] = v;
    }
    for (int idx = tid; idx < WBN; idx += NTHR) {
        int g = idx & 3, qq = (idx >> 2) % HP, k = idx / (4 * HP);
        float v = 0.0f;
        if (qq < H) {
            int row = g * H + qq;
            if (k < HP) { if (k < H) v = Wih1[row * H + k]; }
            else        { int kk = k - HP; if (kk < H) v = Whh1[row * H + kk]; }
        }
        WB[idx] = v;
    }
    for (int idx = tid; idx < S0N; idx += NTHR) s0[idx] = 0.0f;
    for (int idx = tid; idx < S1N; idx += NTHR) s1[idx] = 0.0f;

    // ---- per-thread packed biases for this thread's layer ----
    ull bif, bgo;
    if (q < H) {
        const float* b = grp ? b1 : b0;
        bif = pk2(b[q], b[H + q]);
        bgo = pk2(b[2 * H + q], b[3 * H + q]);
    } else {
        bif = bgo = pk2(0.0f, 0.0f);
    }

    // ---- x(0) into s0.x rows ----
    if (grp == 0 && q < NI) {
        float4 xv;
        xv.x = x[(size_t)(bb0 + 0) * Tt * NI + q];
        xv.y = x[(size_t)(bb0 + 1) * Tt * NI + q];
        xv.z = x[(size_t)(bb0 + 2) * Tt * NI + q];
        xv.w = x[(size_t)(bb0 + 3) * Tt * NI + q];
        *(float4*)(s0 + q * BT + 4 * px) = xv;
    }
    __syncthreads();

    float cst[4] = {0.f, 0.f, 0.f, 0.f};  // this thread's layer cell state
    const int hoff = 4 * px;

    // iteration it: A computes layer0 step it (it < Tt);
    //               B computes layer1 step it-1 (it >= 1).
    // reads use buffer p = it & 1, writes go to nb = (it+1) & 1.
    for (int it = 0; it <= Tt; ++it) {
        const int p  = it & 1;
        const int nb = p ^ 1;
        float hr[4];

        // x prefetch (group A, q<NI), in flight during compute
        float xn0 = 0.f, xn1 = 0.f, xn2 = 0.f, xn3 = 0.f;
        if (grp == 0 && q < NI && it + 1 < Tt) {
            size_t o = (size_t)(it + 1) * NI + q;
            xn0 = x[(size_t)(bb0 + 0) * Tt * NI + o];
            xn1 = x[(size_t)(bb0 + 1) * Tt * NI + o];
            xn2 = x[(size_t)(bb0 + 2) * Tt * NI + o];
            xn3 = x[(size_t)(bb0 + 3) * Tt * NI + o];
        }

        if (grp == 0) {
            if (it < Tt) {
                ull aif[4], ago[4];
                #pragma unroll
                for (int j = 0; j < 4; ++j) { aif[j] = bif; ago[j] = bgo; }
                const float* wa = WA + 4 * q;
                const float* hx = s0 + hoff;                       // x rows
                #pragma unroll
                for (int k = 0; k < NI; ++k) {
                    float4 hv = *(const float4*)(hx + k * BT);
                    ulonglong2 w = *(const ulonglong2*)(wa + k * (4 * HP));
                    ull h0s = splat(hv.x), h1s = splat(hv.y), h2s = splat(hv.z), h3s = splat(hv.w);
                    fma2(aif[0], h0s, w.x); fma2(ago[0], h0s, w.y);
                    fma2(aif[1], h1s, w.x); fma2(ago[1], h1s, w.y);
                    fma2(aif[2], h2s, w.x); fma2(ago[2], h2s, w.y);
                    fma2(aif[3], h3s, w.x); fma2(ago[3], h3s, w.y);
                }
                const float* hh = s0 + (NI + p * HP) * BT + hoff;  // h0 buf p
                const float* wh = WA + NI * (4 * HP) + 4 * q;
                #pragma unroll
                for (int k = 0; k < HP; ++k) {
                    float4 hv = *(const float4*)(hh + k * BT);
                    ulonglong2 w = *(const ulonglong2*)(wh + k * (4 * HP));
                    ull h0s = splat(hv.x), h1s = splat(hv.y), h2s = splat(hv.z), h3s = splat(hv.w);
                    fma2(aif[0], h0s, w.x); fma2(ago[0], h0s, w.y);
                    fma2(aif[1], h1s, w.x); fma2(ago[1], h1s, w.y);
                    fma2(aif[2], h2s, w.x); fma2(ago[2], h2s, w.y);
                    fma2(aif[3], h3s, w.x); fma2(ago[3], h3s, w.y);
                }
                #pragma unroll
                for (int j = 0; j < 4; ++j) {
                    float gi, gf, gg, go;
                    unpk2(aif[j], gi, gf); unpk2(ago[j], gg, go);
                    float i = sigm(gi), f = sigm(gf), g = tanh_(gg), o = sigm(go);
                    cst[j] = f * cst[j] + i * g;
                    hr[j] = o * tanh_(cst[j]);
                }
            }
        } else {
            if (it >= 1) {
                ull aif[4], ago[4];
                #pragma unroll
                for (int j = 0; j < 4; ++j) { aif[j] = bif; ago[j] = bgo; }
                const float* h0b = s1 + p * HP * BT + hoff;        // h0 buf p
                const float* wb0 = WB + 4 * q;
                #pragma unroll
                for (int k = 0; k < HP; ++k) {
                    float4 hv = *(const float4*)(h0b + k * BT);
                    ulonglong2 w = *(const ulonglong2*)(wb0 + k * (4 * HP));
                    ull h0s = splat(hv.x), h1s = splat(hv.y), h2s = splat(hv.z), h3s = splat(hv.w);
                    fma2(aif[0], h0s, w.x); fma2(ago[0], h0s, w.y);
                    fma2(aif[1], h1s, w.x); fma2(ago[1], h1s, w.y);
                    fma2(aif[2], h2s, w.x); fma2(ago[2], h2s, w.y);
                    fma2(aif[3], h3s, w.x); fma2(ago[3], h3s, w.y);
                }
                const float* h1b = s1 + (2 + p) * HP * BT + hoff;  // h1 buf p
                const float* wb1 = WB + HP * (4 * HP) + 4 * q;
                #pragma unroll
                for (int k = 0; k < HP; ++k) {
                    float4 hv = *(const float4*)(h1b + k * BT);
                    ulonglong2 w = *(const ulonglong2*)(wb1 + k * (4 * HP));
                    ull h0s = splat(hv.x), h1s = splat(hv.y), h2s = splat(hv.z), h3s = splat(hv.w);
                    fma2(aif[0], h0s, w.x); fma2(ago[0], h0s, w.y);
                    fma2(aif[1], h1s, w.x); fma2(ago[1], h1s, w.y);
                    fma2(aif[2], h2s, w.x); fma2(ago[2], h2s, w.y);
                    fma2(aif[3], h3s, w.x); fma2(ago[3], h3s, w.y);
                }
                #pragma unroll
                for (int j = 0; j < 4; ++j) {
                    float gi, gf, gg, go;
                    unpk2(aif[j], gi, gf); unpk2(ago[j], gg, go);
                    float i = sigm(gi), f = sigm(gf), g = tanh_(gg), o = sigm(go);
                    cst[j] = f * cst[j] + i * g;
                    hr[j] = o * tanh_(cst[j]);
                }
            }
        }

        __syncthreads();   // all reads of buffers p complete

        if (grp == 0) {
            if (it < Tt) {
                float4 hv4 = make_float4(hr[0], hr[1], hr[2], hr[3]);
                *(float4*)(s0 + (NI + nb * HP + q) * BT + hoff) = hv4;  // next A step
                *(float4*)(s1 + (nb * HP + q) * BT + hoff) = hv4;       // B at it+1
                if (q < NI && it + 1 < Tt)
                    *(float4*)(s0 + q * BT + hoff) = make_float4(xn0, xn1, xn2, xn3);
            }
        } else {
            if (it >= 1)
                *(float4*)(s1 + ((2 + nb) * HP + q) * BT + hoff) =
                    make_float4(hr[0], hr[1], hr[2], hr[3]);
        }

        __syncthreads();   // writes visible for next iteration
    }

    // ---- final projection from h1(T-1) = s1.h1buf[(Tt+1)&1] ----
    if (grp == 0 && q < Cc) {
        const int bufL = (Tt + 1) & 1;
        const float* hl = s1 + (2 + bufL) * HP * BT + hoff;
        float a0 = bc[q], a1 = a0, a2 = a0, a3 = a0;
        #pragma unroll
        for (int k = 0; k < H; ++k) {
            float w = Wc[q * H + k];
            float4 hv = *(const float4*)(hl + k * BT);
            a0 += w * hv.x; a1 += w * hv.y; a2 += w * hv.z; a3 += w * hv.w;
        }
        out[(size_t)(bb0 + 0) * Cc + q] = a0;
        out[(size_t)(bb0 + 1) * Cc + q] = a1;
        out[(size_t)(bb0 + 2) * Cc + q] = a2;
        out[(size_t)(bb0 + 3) * Cc + q] = a3;
    }
}

extern "C" void kernel_launch(void* const* d_in, const int* in_sizes, int n_in,
                              void* d_out, int out_size) {
    const float* x    = (const float*)d_in[0];
    const float* Wih0 = (const float*)d_in[1];
    const float* Whh0 = (const float*)d_in[2];
    const float* b0   = (const float*)d_in[3];
    const float* Wih1 = (const float*)d_in[4];
    const float* Whh1 = (const float*)d_in[5];
    const float* b1   = (const float*)d_in[6];
    const float* Wc   = (const float*)d_in[7];
    const float* bc   = (const float*)d_in[8];

    const int smem_bytes = SMEM_FLOATS * (int)sizeof(float);
    cudaFuncSetAttribute(lstm_kernel, cudaFuncAttributeMaxDynamicSharedMemorySize, smem_bytes);
    lstm_kernel<<<Bsz / BT, NTHR, smem_bytes>>>(
        x, Wih0, Whh0, b0, Wih1, Whh1, b1, Wc, bc, (float*)d_out);
}